// round 1
// baseline (speedup 1.0000x reference)
#include <cuda_runtime.h>

// Problem constants (fixed by the dataset)
#define BB   2
#define LL   4096
#define CC   1024
#define HH   16
#define DD   64
#define KK   13              // kernel size = sqrt(144)+1
#define NBIA (2*KK - 1)      // 25
#define M_ROWS (BB*LL)       // 8192
#define SCALE  0.125f        // D^-0.5 = 1/8

// Scratch (device globals; no runtime allocation allowed)
__device__ float g_qkv[(size_t)M_ROWS * 3 * CC];   // [B*L, 3C] GEMM-natural layout
__device__ float g_att[(size_t)M_ROWS * CC];       // [B*L, C]

// ---------------------------------------------------------------------------
// SGEMM: Cout[M,N] = A[M,K] @ B[K,N] + bias[N]
// 128x128 block tile, BK=8, 256 threads, 8x8 per-thread register tile.
// M,N,K all multiples of tile dims for this problem (no bounds checks).
// ---------------------------------------------------------------------------
__global__ __launch_bounds__(256) void sgemm_bias_kernel(
    const float* __restrict__ A, const float* __restrict__ B,
    const float* __restrict__ bias, float* __restrict__ Cout,
    int M, int N, int K)
{
    __shared__ float As[8][128];
    __shared__ float Bs[8][128];

    const int tid = threadIdx.x;
    const int bx  = blockIdx.x;   // N tile
    const int by  = blockIdx.y;   // M tile
    const int tx  = tid & 15;     // 0..15  -> 8 cols each
    const int ty  = tid >> 4;     // 0..15  -> 8 rows each

    const int aRow = tid >> 1;          // 0..127
    const int aCol = (tid & 1) * 4;     // 0 or 4
    const int bRow = tid >> 5;          // 0..7
    const int bCol = (tid & 31) * 4;    // 0..124

    const float* Ab = A + (size_t)by * 128 * K;
    const float* Bb = B + (size_t)bx * 128;

    float acc[8][8];
    #pragma unroll
    for (int i = 0; i < 8; i++)
        #pragma unroll
        for (int j = 0; j < 8; j++) acc[i][j] = 0.f;

    for (int k0 = 0; k0 < K; k0 += 8) {
        float4 av = *(const float4*)(Ab + (size_t)aRow * K + k0 + aCol);
        float4 bv = *(const float4*)(Bb + (size_t)(k0 + bRow) * N + bCol);
        __syncthreads();   // previous tile fully consumed before overwrite
        As[aCol + 0][aRow] = av.x;
        As[aCol + 1][aRow] = av.y;
        As[aCol + 2][aRow] = av.z;
        As[aCol + 3][aRow] = av.w;
        *(float4*)(&Bs[bRow][bCol]) = bv;
        __syncthreads();

        #pragma unroll
        for (int k = 0; k < 8; k++) {
            float4 a0 = *(const float4*)(&As[k][ty * 8]);
            float4 a1 = *(const float4*)(&As[k][ty * 8 + 4]);
            float4 b0 = *(const float4*)(&Bs[k][tx * 8]);
            float4 b1 = *(const float4*)(&Bs[k][tx * 8 + 4]);
            float a[8] = {a0.x, a0.y, a0.z, a0.w, a1.x, a1.y, a1.z, a1.w};
            float b[8] = {b0.x, b0.y, b0.z, b0.w, b1.x, b1.y, b1.z, b1.w};
            #pragma unroll
            for (int i = 0; i < 8; i++)
                #pragma unroll
                for (int j = 0; j < 8; j++)
                    acc[i][j] = fmaf(a[i], b[j], acc[i][j]);
        }
    }

    const int colBase = bx * 128 + tx * 8;
    float bs[8];
    #pragma unroll
    for (int j = 0; j < 8; j++) bs[j] = bias[colBase + j];

    #pragma unroll
    for (int i = 0; i < 8; i++) {
        int row = by * 128 + ty * 8 + i;
        float4 o0 = make_float4(acc[i][0] + bs[0], acc[i][1] + bs[1],
                                acc[i][2] + bs[2], acc[i][3] + bs[3]);
        float4 o1 = make_float4(acc[i][4] + bs[4], acc[i][5] + bs[5],
                                acc[i][6] + bs[6], acc[i][7] + bs[7]);
        float* cp = Cout + (size_t)row * N + colBase;
        *(float4*)(cp)     = o0;
        *(float4*)(cp + 4) = o1;
    }
}

// ---------------------------------------------------------------------------
// Neighborhood attention: one warp per (b, h, l).
// qkv layout: [(b*L + l), which*C + h*D + d], which in {0=q,1=k,2=v}
// out layout: g_att[(b*L + l)*C + h*D + d]   (proj-GEMM ready)
// ---------------------------------------------------------------------------
__global__ __launch_bounds__(256) void natt_kernel(const float* __restrict__ rpb)
{
    const int gid  = blockIdx.x * blockDim.x + threadIdx.x;
    const int lane = gid & 31;
    const int gw   = gid >> 5;          // 0 .. B*H*L-1
    const int l    = gw % LL;
    const int h    = (gw / LL) % HH;
    const int b    = gw / (LL * HH);

    int start = l - KK / 2;
    if (start < 0) start = 0;
    if (start > LL - KK) start = LL - KK;

    const size_t rowStride = (size_t)3 * CC;
    const float* q_ptr = g_qkv + (size_t)(b * LL + l) * rowStride + h * DD;
    const float2 q2 = ((const float2*)q_ptr)[lane];

    // scores
    float s[KK];
    #pragma unroll
    for (int j = 0; j < KK; j++) {
        const int idx = start + j;
        const float* k_ptr = g_qkv + (size_t)(b * LL + idx) * rowStride + CC + h * DD;
        const float2 k2 = ((const float2*)k_ptr)[lane];
        float p = q2.x * k2.x + q2.y * k2.y;
        #pragma unroll
        for (int m = 16; m > 0; m >>= 1)
            p += __shfl_xor_sync(0xffffffff, p, m);
        s[j] = p * SCALE + rpb[h * NBIA + (idx - l + KK - 1)];
    }

    // softmax over KK (replicated across lanes)
    float mx = s[0];
    #pragma unroll
    for (int j = 1; j < KK; j++) mx = fmaxf(mx, s[j]);
    float denom = 0.f;
    #pragma unroll
    for (int j = 0; j < KK; j++) { s[j] = expf(s[j] - mx); denom += s[j]; }
    const float inv = 1.f / denom;

    // weighted V sum
    float2 acc = make_float2(0.f, 0.f);
    #pragma unroll
    for (int j = 0; j < KK; j++) {
        const int idx = start + j;
        const float* v_ptr = g_qkv + (size_t)(b * LL + idx) * rowStride + 2 * CC + h * DD;
        const float2 v2 = ((const float2*)v_ptr)[lane];
        const float p = s[j] * inv;
        acc.x = fmaf(p, v2.x, acc.x);
        acc.y = fmaf(p, v2.y, acc.y);
    }

    float* o_ptr = g_att + (size_t)(b * LL + l) * CC + h * DD;
    ((float2*)o_ptr)[lane] = acc;
}

// ---------------------------------------------------------------------------
extern "C" void kernel_launch(void* const* d_in, const int* in_sizes, int n_in,
                              void* d_out, int out_size)
{
    const float* x      = (const float*)d_in[0];  // [B,L,C]
    const float* w_qkv  = (const float*)d_in[1];  // [C,3C]
    const float* b_qkv  = (const float*)d_in[2];  // [3C]
    const float* rpb    = (const float*)d_in[3];  // [H,25]
    const float* w_proj = (const float*)d_in[4];  // [C,C]
    const float* b_proj = (const float*)d_in[5];  // [C]
    float*       out    = (float*)d_out;          // [B,L,C]

    float* qkv_buf = nullptr;
    float* att_buf = nullptr;
    cudaGetSymbolAddress((void**)&qkv_buf, g_qkv);
    cudaGetSymbolAddress((void**)&att_buf, g_att);

    // 1) QKV projection: [8192,1024] @ [1024,3072] + bias
    {
        dim3 grid(3 * CC / 128, M_ROWS / 128);
        sgemm_bias_kernel<<<grid, 256>>>(x, w_qkv, b_qkv, qkv_buf,
                                         M_ROWS, 3 * CC, CC);
    }

    // 2) neighborhood attention: one warp per (b,h,l)
    {
        const int totalWarps = BB * HH * LL;
        dim3 grid(totalWarps * 32 / 256);
        natt_kernel<<<grid, 256>>>(rpb);
    }

    // 3) output projection: [8192,1024] @ [1024,1024] + bias
    {
        dim3 grid(CC / 128, M_ROWS / 128);
        sgemm_bias_kernel<<<grid, 256>>>(att_buf, w_proj, b_proj, out,
                                         M_ROWS, CC, CC);
    }
}